// round 17
// baseline (speedup 1.0000x reference)
#include <cuda_runtime.h>
#include <cstdint>

#define S_LEN 101
#define BATCH 2048
#define HID 200
#define DIN 120
#define DOUT 12
#define M_TOTAL (S_LEN * BATCH)   // 206848

// Scratch (no allocations allowed -> __device__ globals)
__device__ float g_cur[(size_t)M_TOTAL * HID];        // ~165 MB  cur[b][t][n]
__device__ uint4 g_bfg[148][8][10][32];               // B-frags nf 15..24, per CTA

typedef unsigned long long ull;

// ---------- packed f32x2 helpers ----------
__device__ __forceinline__ ull pack2(float lo, float hi) {
    ull r; asm("mov.b64 %0, {%1,%2};" : "=l"(r) : "f"(lo), "f"(hi)); return r;
}
__device__ __forceinline__ void unpack2(ull v, float& lo, float& hi) {
    asm("mov.b64 {%0,%1}, %2;" : "=f"(lo), "=f"(hi) : "l"(v));
}
__device__ __forceinline__ ull add2(ull a, ull b) {
    ull d; asm("add.rn.f32x2 %0, %1, %2;" : "=l"(d) : "l"(a), "l"(b)); return d;
}

// ---------- bf16 / mma helpers ----------
__device__ __forceinline__ unsigned bf16x2of(float lo, float hi) {
    unsigned r; asm("cvt.rn.bf16x2.f32 %0, %1, %2;" : "=r"(r) : "f"(hi), "f"(lo));
    return r;   // lo -> bits[0:16), hi -> bits[16:32)
}
__device__ __forceinline__ void bf16_hilo(float x0, float x1, unsigned& h, unsigned& l) {
    h = bf16x2of(x0, x1);
    float h0 = __uint_as_float(h << 16);
    float h1 = __uint_as_float(h & 0xffff0000u);
    l = bf16x2of(x0 - h0, x1 - h1);
}
__device__ __forceinline__ void mma_bf16(float* c,
                                         unsigned a0, unsigned a1, unsigned a2, unsigned a3,
                                         unsigned b0, unsigned b1) {
    asm volatile(
        "mma.sync.aligned.m16n8k16.row.col.f32.bf16.bf16.f32 "
        "{%0,%1,%2,%3}, {%4,%5,%6,%7}, {%8,%9}, {%0,%1,%2,%3};"
        : "+f"(c[0]), "+f"(c[1]), "+f"(c[2]), "+f"(c[3])
        : "r"(a0), "r"(a1), "r"(a2), "r"(a3), "r"(b0), "r"(b1));
}
__device__ __forceinline__ float bfLO(unsigned u) { return __uint_as_float(u << 16); }
__device__ __forceinline__ float bfHI(unsigned u) { return __uint_as_float(u & 0xffff0000u); }

// ================= fused kernel configuration ================================
#define NLIFW 14                                   // consumer warps (1 batch each)
#define NPRODW 4                                   // producer warps
#define FT_THREADS ((NLIFW + NPRODW) * 32)         // 576
#define NFRAG 25                                   // n-fragments (N=200)
#define NFS 15                                     // n-frags cached in smem
#define SLAB 13
#define NSLAB 8                                    // 8*13 = 104 >= 101
#define LROWS 201
#define LSTRIDE (LROWS * 100)                      // u32 words per W layer
#define DYN_SMEM (2 * LSTRIDE * 4 + 8 * NFS * 32 * 16)   // 160800+61440 = 222240

#define CTA_BAR() asm volatile("bar.sync 0, 576;" ::: "memory")

// Warp-uniform sparse scan, 2 spikes per iteration (2nd slot -> zero row 200).
__device__ __forceinline__ void scan8bf(const unsigned* mk, const uint4* Wbase,
                                        int lidx, ull* acc) {
    #pragma unroll
    for (int m = 0; m < 8; m++) {
        unsigned u = mk[m];
        while (u) {                                   // uniform across warp
            int j0 = __ffs(u) - 1;
            u &= u - 1;
            int j1 = __ffs(u);                        // 0 if empty
            int h0 = 8 * j0 + m;
            int h1 = j1 ? 8 * (j1 - 1) + m : 200;     // 200 = zero row
            u = j1 ? (u & (u - 1)) : 0u;
            const uint4 w0 = Wbase[h0 * 25 + lidx];
            const uint4 w1 = Wbase[h1 * 25 + lidx];
            acc[0] = add2(acc[0], pack2(bfLO(w0.x), bfHI(w0.x)));
            acc[1] = add2(acc[1], pack2(bfLO(w0.y), bfHI(w0.y)));
            acc[2] = add2(acc[2], pack2(bfLO(w0.z), bfHI(w0.z)));
            acc[3] = add2(acc[3], pack2(bfLO(w0.w), bfHI(w0.w)));
            acc[0] = add2(acc[0], pack2(bfLO(w1.x), bfHI(w1.x)));
            acc[1] = add2(acc[1], pack2(bfLO(w1.y), bfHI(w1.y)));
            acc[2] = add2(acc[2], pack2(bfLO(w1.z), bfHI(w1.z)));
            acc[3] = add2(acc[3], pack2(bfLO(w1.w), bfHI(w1.w)));
        }
    }
}

__global__ __launch_bounds__(FT_THREADS, 1)
void snn_fused_kernel(const float* __restrict__ x,  const float* __restrict__ W1,
                      const float* __restrict__ b1, const float* __restrict__ W2,
                      const float* __restrict__ b2, const float* __restrict__ W3,
                      const float* __restrict__ b3, const float* __restrict__ Wr,
                      const float* __restrict__ br, float* __restrict__ out) {
    extern __shared__ unsigned smw[];
    const uint4* W2b = (const uint4*)smw;               // bf16 row h at +h*25 uint4
    const uint4* W3b = (const uint4*)(smw + LSTRIDE);
    uint4* Bf_s = (uint4*)(smw + 2 * LSTRIDE);          // [8][NFS][32]
    __shared__ unsigned char cnt_sm[NLIFW][HID];

    const int tid   = threadIdx.x;
    const int warp  = tid >> 5;
    const int lane  = tid & 31;
    const int group = lane >> 2;
    const int tg    = lane & 3;
    const int b0    = blockIdx.x * NLIFW;

    // ---- init: W2/W3 bf16 -> smem (+zero row 200) ----
    for (int i = tid; i < HID * HID / 2; i += FT_THREADS) {
        float2 a2 = *(const float2*)(W2 + 2 * i);
        float2 a3 = *(const float2*)(W3 + 2 * i);
        smw[i]           = bf16x2of(a2.x, a2.y);
        smw[LSTRIDE + i] = bf16x2of(a3.x, a3.y);
    }
    for (int i = tid; i < 100; i += FT_THREADS) {
        smw[HID * HID / 2 + i]           = 0u;
        smw[LSTRIDE + HID * HID / 2 + i] = 0u;
    }
    // ---- init: W1 -> fragment-native bf16 hi/lo tables (smem + per-CTA gmem) ----
    for (int idx = tid; idx < 8 * NFRAG * 32; idx += FT_THREADS) {
        int ks  = idx / (NFRAG * 32);
        int rem = idx - ks * NFRAG * 32;
        int nf  = rem >> 5;
        int t   = rem & 31;
        int g = t >> 2, q = t & 3;
        int n  = nf * 8 + g;
        int k0 = ks * 16 + 2 * q;
        int k1 = k0 + 8;
        float w00 = W1[k0 * HID + n];
        float w01 = W1[(k0 + 1) * HID + n];
        float w10 = (k1     < DIN) ? W1[k1 * HID + n]       : 0.f;
        float w11 = (k1 + 1 < DIN) ? W1[(k1 + 1) * HID + n] : 0.f;
        unsigned h0, l0, h1, l1;
        bf16_hilo(w00, w01, h0, l0);
        bf16_hilo(w10, w11, h1, l1);
        uint4 v = make_uint4(h0, h1, l0, l1);
        if (nf < NFS) Bf_s[(ks * NFS + nf) * 32 + t] = v;
        else          g_bfg[blockIdx.x][ks][nf - NFS][t] = v;
    }
    __syncthreads();

    if (warp >= NLIFW) {
        // ========================= PRODUCER warps ============================
        const int pw  = warp - NLIFW;                  // 0..3
        const int nf0 = pw * 7;                        // 0,7,14,21
        const int nfw = (pw < 3) ? 7 : 4;
        for (int s = 0; s <= NSLAB; s++) {
            if (s < NSLAB) {
                const int  t_lo = s * SLAB + group;
                const int  t_hi = t_lo + 8;
                const bool vlo  = (t_lo < S_LEN);
                const bool vhi  = (group < 5) && (t_hi < S_LEN);
                float2 bias[7];
                #pragma unroll
                for (int i = 0; i < 7; i++)
                    bias[i] = (i < nfw) ? *(const float2*)(b1 + (nf0 + i) * 8 + 2 * tg)
                                        : make_float2(0.f, 0.f);
                for (int p = 0; p < 7; p++) {          // 2 batches per pass
                    const int  bA = b0 + 2 * p, bB = bA + 1;
                    const bool vA = (bA < BATCH), vB = (bB < BATCH);
                    const float* xAl = x + (size_t)(bA * 303 + t_lo) * 40;
                    const float* xAh = x + (size_t)(bA * 303 + t_hi) * 40;
                    const float* xBl = x + (size_t)(bB * 303 + t_lo) * 40;
                    const float* xBh = x + (size_t)(bB * 303 + t_hi) * 40;

                    float aA[7][4], aB[7][4];
                    #pragma unroll
                    for (int i = 0; i < 7; i++) {
                        aA[i][0] = bias[i].x; aA[i][1] = bias[i].y;
                        aA[i][2] = bias[i].x; aA[i][3] = bias[i].y;
                        aB[i][0] = bias[i].x; aB[i][1] = bias[i].y;
                        aB[i][2] = bias[i].x; aB[i][3] = bias[i].y;
                    }

                    #pragma unroll
                    for (int ks = 0; ks < 8; ks++) {
                        const int ka = ks * 16 + 2 * tg;
                        const int ca = ka / 40, ma = ka - ca * 40;
                        const int oa = ca * 4040 + ma;
                        const float2 z = make_float2(0.f, 0.f);
                        float2 A0 = (vA && vlo) ? *(const float2*)(xAl + oa) : z;
                        float2 A1 = (vA && vhi) ? *(const float2*)(xAh + oa) : z;
                        float2 B0 = (vB && vlo) ? *(const float2*)(xBl + oa) : z;
                        float2 B1 = (vB && vhi) ? *(const float2*)(xBh + oa) : z;
                        float2 A2 = z, A3 = z, B2 = z, B3 = z;
                        if (ks < 7) {
                            const int kb = ka + 8;
                            const int cb = kb / 40, mb = kb - cb * 40;
                            const int ob = cb * 4040 + mb;
                            A2 = (vA && vlo) ? *(const float2*)(xAl + ob) : z;
                            A3 = (vA && vhi) ? *(const float2*)(xAh + ob) : z;
                            B2 = (vB && vlo) ? *(const float2*)(xBl + ob) : z;
                            B3 = (vB && vhi) ? *(const float2*)(xBh + ob) : z;
                        }
                        unsigned hA0,lA0,hA1,lA1,hA2,lA2,hA3,lA3;
                        unsigned hB0,lB0,hB1,lB1,hB2,lB2,hB3,lB3;
                        bf16_hilo(A0.x, A0.y, hA0, lA0);
                        bf16_hilo(A1.x, A1.y, hA1, lA1);
                        bf16_hilo(A2.x, A2.y, hA2, lA2);
                        bf16_hilo(A3.x, A3.y, hA3, lA3);
                        bf16_hilo(B0.x, B0.y, hB0, lB0);
                        bf16_hilo(B1.x, B1.y, hB1, lB1);
                        bf16_hilo(B2.x, B2.y, hB2, lB2);
                        bf16_hilo(B3.x, B3.y, hB3, lB3);

                        #pragma unroll
                        for (int i = 0; i < 7; i++) {
                            if (i < nfw) {
                                const int nf = nf0 + i;
                                uint4 bf = (nf < NFS)
                                    ? Bf_s[(ks * NFS + nf) * 32 + lane]
                                    : __ldg(&g_bfg[blockIdx.x][ks][nf - NFS][lane]);
                                mma_bf16(aA[i], hA0, hA1, hA2, hA3, bf.x, bf.y);
                                mma_bf16(aA[i], hA0, hA1, hA2, hA3, bf.z, bf.w);
                                mma_bf16(aA[i], lA0, lA1, lA2, lA3, bf.x, bf.y);
                                mma_bf16(aB[i], hB0, hB1, hB2, hB3, bf.x, bf.y);
                                mma_bf16(aB[i], hB0, hB1, hB2, hB3, bf.z, bf.w);
                                mma_bf16(aB[i], lB0, lB1, lB2, lB3, bf.x, bf.y);
                            }
                        }
                    }

                    #pragma unroll
                    for (int i = 0; i < 7; i++) {
                        if (i < nfw) {
                            const int c = (nf0 + i) * 8 + 2 * tg;
                            if (vA && vlo)
                                *(float2*)(g_cur + (size_t)(bA * S_LEN + t_lo) * HID + c)
                                    = make_float2(aA[i][0], aA[i][1]);
                            if (vA && vhi)
                                *(float2*)(g_cur + (size_t)(bA * S_LEN + t_hi) * HID + c)
                                    = make_float2(aA[i][2], aA[i][3]);
                            if (vB && vlo)
                                *(float2*)(g_cur + (size_t)(bB * S_LEN + t_lo) * HID + c)
                                    = make_float2(aB[i][0], aB[i][1]);
                            if (vB && vhi)
                                *(float2*)(g_cur + (size_t)(bB * S_LEN + t_hi) * HID + c)
                                    = make_float2(aB[i][2], aB[i][3]);
                        }
                    }
                }
                __threadfence_block();                 // order STGs before bar
            }
            CTA_BAR();
        }
    } else {
        // ========================= CONSUMER (lif) warps ======================
        const bool iv   = (lane < 25);
        const int  lidx = iv ? lane : 0;
        const int  b    = b0 + warp;
        const bool active = (b < BATCH);               // warp-uniform
        ull bias2[4] = {0,0,0,0}, bias3[4] = {0,0,0,0};
        if (iv) {
            #pragma unroll
            for (int q = 0; q < 4; q++) {
                float2 u2 = *(const float2*)(b2 + 8 * lane + 2 * q);
                float2 u3 = *(const float2*)(b3 + 8 * lane + 2 * q);
                bias2[q] = pack2(u2.x, u2.y);
                bias3[q] = pack2(u3.x, u3.y);
            }
        }
        float v1[8], v2[8], v3[8];
        int cnt[8];
        #pragma unroll
        for (int e = 0; e < 8; e++) { v1[e]=0.f; v2[e]=0.f; v3[e]=0.f; cnt[e]=0; }
        const float* curb = g_cur + (size_t)b * S_LEN * HID + (iv ? 8 * lane : 0);

        for (int s = 0; s <= NSLAB; s++) {
            if (s >= 1 && active) {
                const int t0   = (s - 1) * SLAB;
                const int tend = (t0 + SLAB < S_LEN) ? t0 + SLAB : S_LEN;
                float4 cA = *(const float4*)(curb + (size_t)t0 * HID);
                float4 cB = *(const float4*)(curb + (size_t)t0 * HID + 4);
                for (int t = t0; t < tend; t++) {
                    float4 nA = cA, nB = cB;
                    if (t + 1 < tend) {                // slab-local prefetch
                        nA = *(const float4*)(curb + (size_t)(t + 1) * HID);
                        nB = *(const float4*)(curb + (size_t)(t + 1) * HID + 4);
                    }
                    float a[8] = { cA.x, cA.y, cA.z, cA.w, cB.x, cB.y, cB.z, cB.w };

                    unsigned mk1[8];
                    #pragma unroll
                    for (int e = 0; e < 8; e++) {
                        v1[e] = 0.5f * (v1[e] + a[e]);
                        bool sp = iv && (v1[e] >= 1.0f);
                        if (sp) v1[e] = 0.f;
                        mk1[e] = __ballot_sync(0xffffffffu, sp);
                    }

                    ull acc[4] = { bias2[0], bias2[1], bias2[2], bias2[3] };
                    scan8bf(mk1, W2b, lidx, acc);
                    float c[8];
                    unpack2(acc[0], c[0], c[1]); unpack2(acc[1], c[2], c[3]);
                    unpack2(acc[2], c[4], c[5]); unpack2(acc[3], c[6], c[7]);

                    unsigned mk2[8];
                    #pragma unroll
                    for (int e = 0; e < 8; e++) {
                        v2[e] = 0.5f * (v2[e] + c[e]);
                        bool sp = iv && (v2[e] >= 1.0f);
                        if (sp) v2[e] = 0.f;
                        mk2[e] = __ballot_sync(0xffffffffu, sp);
                    }

                    ull acc3[4] = { bias3[0], bias3[1], bias3[2], bias3[3] };
                    scan8bf(mk2, W3b, lidx, acc3);
                    float d[8];
                    unpack2(acc3[0], d[0], d[1]); unpack2(acc3[1], d[2], d[3]);
                    unpack2(acc3[2], d[4], d[5]); unpack2(acc3[3], d[6], d[7]);

                    #pragma unroll
                    for (int e = 0; e < 8; e++) {
                        v3[e] = 0.5f * (v3[e] + d[e]);
                        if (v3[e] >= 1.0f) { v3[e] = 0.f; cnt[e]++; }
                    }
                    cA = nA; cB = nB;
                }
            }
            CTA_BAR();
        }

        // ---- fused readout + log_softmax (per-warp; cnt_sm row owned by warp)
        if (active) {
            if (iv) {
                #pragma unroll
                for (int e = 0; e < 8; e++)
                    cnt_sm[warp][8 * lane + e] = (unsigned char)cnt[e];
            }
            __syncwarp();
            float o = -3.0e38f;
            if (lane < DOUT) {
                float acc = 0.f;
                #pragma unroll 4
                for (int k = 0; k < HID; k++)
                    acc += (float)cnt_sm[warp][k] * Wr[k * DOUT + lane];
                o = acc * (1.0f / 101.0f) + br[lane];
            }
            float mx = o;
            #pragma unroll
            for (int off = 16; off; off >>= 1)
                mx = fmaxf(mx, __shfl_xor_sync(0xffffffffu, mx, off));
            float e = (lane < DOUT) ? expf(o - mx) : 0.f;
            float ssum = e;
            #pragma unroll
            for (int off = 16; off; off >>= 1)
                ssum += __shfl_xor_sync(0xffffffffu, ssum, off);
            if (lane < DOUT) out[b * DOUT + lane] = (o - mx) - logf(ssum);
        }
    }
}

// ================= launch ====================================================
extern "C" void kernel_launch(void* const* d_in, const int* in_sizes, int n_in,
                              void* d_out, int out_size) {
    const float* x  = (const float*)d_in[0];
    const float* W1 = (const float*)d_in[1];
    const float* b1 = (const float*)d_in[2];
    const float* W2 = (const float*)d_in[3];
    const float* b2 = (const float*)d_in[4];
    const float* W3 = (const float*)d_in[5];
    const float* b3 = (const float*)d_in[6];
    const float* Wr = (const float*)d_in[7];
    const float* br = (const float*)d_in[8];
    float* out = (float*)d_out;

    cudaFuncSetAttribute(snn_fused_kernel,
                         cudaFuncAttributeMaxDynamicSharedMemorySize, DYN_SMEM);

    const int grid = (BATCH + NLIFW - 1) / NLIFW;      // 147
    snn_fused_kernel<<<grid, FT_THREADS, DYN_SMEM>>>(x, W1, b1, W2, b2,
                                                     W3, b3, Wr, br, out);
}